// round 7
// baseline (speedup 1.0000x reference)
#include <cuda_runtime.h>
#include <cuda_bf16.h>
#include <math.h>
#include <stdint.h>

// ---------------------------------------------------------------------------
// NSF coupling layer on GB300 (compute_103-safe tensor path).
//   GEMMs via mma.sync.m16n8k16 bf16 (HMMA), 3-term split precision:
//     D = Ah*Bh + Ah*Bl + Al*Bh   (fp32 register accumulation)
//   512-thread CTAs (16 warps, warp tile 32x32) for latency hiding.
//   3-stage cp.async pipeline, ldmatrix with XOR-swizzled SMEM.
// ---------------------------------------------------------------------------

#define MAXB 32768
#define HD   512
#define PDIM 1472
#define PPAD 1536

// ------------------------- scratch (device globals) ------------------------
__device__ __align__(128) __nv_bfloat16 g_xl_hi[(size_t)MAXB * 64];
__device__ __align__(128) __nv_bfloat16 g_xl_lo[(size_t)MAXB * 64];
__device__ __align__(128) __nv_bfloat16 g_up_hi[(size_t)MAXB * 64];
__device__ __align__(128) __nv_bfloat16 g_up_lo[(size_t)MAXB * 64];
__device__ __align__(128) __nv_bfloat16 g_hA_hi[(size_t)MAXB * HD];
__device__ __align__(128) __nv_bfloat16 g_hA_lo[(size_t)MAXB * HD];
__device__ __align__(128) __nv_bfloat16 g_hB_hi[(size_t)MAXB * HD];
__device__ __align__(128) __nv_bfloat16 g_hB_lo[(size_t)MAXB * HD];
__device__ __align__(128) float g_params[(size_t)MAXB * PDIM];
__device__ __align__(128) float g_ld[MAXB];
__device__ __align__(128) __nv_bfloat16 g_w1t_hi[512 * 64];
__device__ __align__(128) __nv_bfloat16 g_w1t_lo[512 * 64];
__device__ __align__(128) __nv_bfloat16 g_w2t_hi[512 * 512];
__device__ __align__(128) __nv_bfloat16 g_w2t_lo[512 * 512];
__device__ __align__(128) __nv_bfloat16 g_w3t_hi[PPAD * 512];
__device__ __align__(128) __nv_bfloat16 g_w3t_lo[PPAD * 512];

// ------------------------- low-level helpers -------------------------------
__device__ __forceinline__ uint32_t smem_u32(const void* p) {
    uint32_t a;
    asm("{ .reg .u64 t; cvta.to.shared.u64 t, %1; cvt.u32.u64 %0, t; }"
        : "=r"(a) : "l"(p));
    return a;
}

__device__ __forceinline__ void ldsm4(uint32_t* r, uint32_t addr) {
    asm volatile("ldmatrix.sync.aligned.m8n8.x4.shared.b16 {%0,%1,%2,%3}, [%4];"
                 : "=r"(r[0]), "=r"(r[1]), "=r"(r[2]), "=r"(r[3]) : "r"(addr));
}

__device__ __forceinline__ void mma16816(float* c, const uint32_t* a,
                                         const uint32_t* b) {
    asm volatile(
        "mma.sync.aligned.m16n8k16.row.col.f32.bf16.bf16.f32 "
        "{%0,%1,%2,%3}, {%4,%5,%6,%7}, {%8,%9}, {%0,%1,%2,%3};"
        : "+f"(c[0]), "+f"(c[1]), "+f"(c[2]), "+f"(c[3])
        : "r"(a[0]), "r"(a[1]), "r"(a[2]), "r"(a[3]), "r"(b[0]), "r"(b[1]));
}

#define CP_ASYNC16(sa, gp) \
    asm volatile("cp.async.cg.shared.global [%0], [%1], 16;" :: "r"(sa), "l"(gp))
#define CP_COMMIT() asm volatile("cp.async.commit_group;" ::: "memory")
#define CP_WAIT1()  asm volatile("cp.async.wait_group 1;" ::: "memory")

// ---------------------------------------------------------------------------
// HMMA GEMM:  C[M, Nreal] = A[M,K] @ Wt[Npad,K]^T + bias  (opt SiLU)
// CTA 128x128, BK=32, 16 warps (4 M x 4 N), warp tile 32x32.
// SMEM per matrix tile: 128 rows x 32 bf16 (64 B/row), XOR-swizzled 16B chunks:
//   phys = row*64 + ((chunk ^ ((row>>1)&3)) << 4)
// Stage = {Ah, Al, Bh, Bl} = 4 * 8KB = 32KB; three stages = 96KB.
// ---------------------------------------------------------------------------
#define STAGE_BYTES 32768

__device__ __forceinline__ void load_stage(
    uint32_t sbase,
    const __nv_bfloat16* ah, const __nv_bfloat16* al,
    const __nv_bfloat16* bh, const __nv_bfloat16* bl,
    int lda, int ldb, int tid)
{
#pragma unroll
    for (int it = 0; it < 4; it++) {
        const int idx = it * 512 + tid;
        const int mat = idx >> 9;        // one matrix per iteration
        const int cid = idx & 511;
        const int row = cid >> 2;
        const int ch  = cid & 3;
        const int ld  = (mat < 2) ? lda : ldb;
        const __nv_bfloat16* g =
            (mat == 0) ? ah : (mat == 1) ? al : (mat == 2) ? bh : bl;
        const void* gp = g + (size_t)row * ld + ch * 8;
        const uint32_t sa =
            sbase + mat * 8192 + row * 64 + ((ch ^ ((row >> 1) & 3)) << 4);
        CP_ASYNC16(sa, gp);
    }
}

template <int ACT, int SPLIT>
__global__ __launch_bounds__(512)
void gemm_hmma(const __nv_bfloat16* __restrict__ Ah,
               const __nv_bfloat16* __restrict__ Al, int lda,
               const __nv_bfloat16* __restrict__ Bh,
               const __nv_bfloat16* __restrict__ Bl,
               const float* __restrict__ bias,
               float* __restrict__ outf,
               __nv_bfloat16* __restrict__ oh,
               __nv_bfloat16* __restrict__ ol,
               int Nreal, int K)
{
    extern __shared__ char smem[];
    const uint32_t sbase = smem_u32(smem);

    const int tid  = threadIdx.x;
    const int lane = tid & 31;
    const int wid  = tid >> 5;           // 0..15
    const int warp_m = (wid >> 2) * 32;  // 0,32,64,96
    const int warp_n = (wid & 3) * 32;   // 0,32,64,96
    const int m0 = blockIdx.y * 128;
    const int n0 = blockIdx.x * 128;

    const __nv_bfloat16* Ahp = Ah + (size_t)m0 * lda;
    const __nv_bfloat16* Alp = Al + (size_t)m0 * lda;
    const __nv_bfloat16* Bhp = Bh + (size_t)n0 * K;
    const __nv_bfloat16* Blp = Bl + (size_t)n0 * K;

    float acc[2][4][4];
#pragma unroll
    for (int i = 0; i < 2; i++)
#pragma unroll
        for (int j = 0; j < 4; j++)
#pragma unroll
            for (int q = 0; q < 4; q++) acc[i][j][q] = 0.f;

    const int nk = K >> 5;  // BK = 32

    // prologue: prefetch stages 0 and 1 (each its own commit group)
    load_stage(sbase, Ahp, Alp, Bhp, Blp, lda, K, tid);
    CP_COMMIT();
    if (nk > 1) {
        load_stage(sbase + STAGE_BYTES, Ahp + 32, Alp + 32, Bhp + 32, Blp + 32,
                   lda, K, tid);
    }
    CP_COMMIT();

    int buf = 0;
    for (int kc = 0; kc < nk; kc++) {
        CP_WAIT1();           // stage kc arrived (<=1 group still in flight)
        __syncthreads();      // visibility + all warps done reading prev buf

        // prefetch stage kc+2 into buffer (kc+2)%3 (last read at kc-1; safe)
        if (kc + 2 < nk) {
            const int ko = (kc + 2) * 32;
            int nbuf = buf + 2; if (nbuf >= 3) nbuf -= 3;
            load_stage(sbase + nbuf * STAGE_BYTES,
                       Ahp + ko, Alp + ko, Bhp + ko, Blp + ko, lda, K, tid);
        }
        CP_COMMIT();          // always commit (keeps group count invariant)

        const uint32_t st = sbase + buf * STAGE_BYTES;
        const uint32_t aH = st, aL = st + 8192, bH = st + 16384, bL = st + 24576;

#pragma unroll
        for (int s = 0; s < 2; s++) {  // two k16 steps per chunk
            uint32_t ah[2][4], al[2][4];
            const int chA = s * 2 + (lane >> 4);
#pragma unroll
            for (int i = 0; i < 2; i++) {
                const int r = warp_m + i * 16 + (lane & 15);
                const uint32_t off = r * 64 + ((chA ^ ((r >> 1) & 3)) << 4);
                ldsm4(ah[i], aH + off);
                ldsm4(al[i], aL + off);
            }
            uint32_t bh[2][4], bl[2][4];
            const int chB = s * 2 + ((lane >> 3) & 1);
#pragma unroll
            for (int j2 = 0; j2 < 2; j2++) {
                const int n = warp_n + j2 * 16 + (lane & 7) + ((lane >> 4) << 3);
                const uint32_t off = n * 64 + ((chB ^ ((n >> 1) & 3)) << 4);
                ldsm4(bh[j2], bH + off);
                ldsm4(bl[j2], bL + off);
            }
#pragma unroll
            for (int i = 0; i < 2; i++)
#pragma unroll
                for (int j = 0; j < 4; j++) {
                    float* c = acc[i][j];
                    const uint32_t* pbh = &bh[j >> 1][(j & 1) * 2];
                    const uint32_t* pbl = &bl[j >> 1][(j & 1) * 2];
                    mma16816(c, ah[i], pbh);   // Ah*Bh
                    mma16816(c, ah[i], pbl);   // Ah*Bl
                    mma16816(c, al[i], pbh);   // Al*Bh
                }
        }
        buf++; if (buf == 3) buf = 0;
    }

    // ---- epilogue: bias + opt SiLU + store (fp32 or bf16 hi/lo split) ----
#pragma unroll
    for (int i = 0; i < 2; i++) {
        const int r0 = m0 + warp_m + i * 16 + (lane >> 2);
#pragma unroll
        for (int j = 0; j < 4; j++) {
            const int col = n0 + warp_n + j * 8 + ((lane & 3) << 1);
            if (col < Nreal) {
                const float b0 = bias[col];
                const float b1 = bias[col + 1];
#pragma unroll
                for (int h = 0; h < 2; h++) {
                    const int r = r0 + h * 8;
                    float v0 = acc[i][j][h * 2 + 0] + b0;
                    float v1 = acc[i][j][h * 2 + 1] + b1;
                    if (ACT) {
                        v0 = v0 / (1.f + __expf(-v0));
                        v1 = v1 / (1.f + __expf(-v1));
                    }
                    const size_t ob = (size_t)r * Nreal + col;
                    if (SPLIT) {
                        const __nv_bfloat16 h0 = __float2bfloat16(v0);
                        const __nv_bfloat16 h1 = __float2bfloat16(v1);
                        *reinterpret_cast<__nv_bfloat162*>(oh + ob) =
                            __halves2bfloat162(h0, h1);
                        *reinterpret_cast<__nv_bfloat162*>(ol + ob) =
                            __halves2bfloat162(
                                __float2bfloat16(v0 - __bfloat162float(h0)),
                                __float2bfloat16(v1 - __bfloat162float(h1)));
                    } else {
                        float2 v; v.x = v0; v.y = v1;
                        *reinterpret_cast<float2*>(outf + ob) = v;
                    }
                }
            }
        }
    }
}

// ---------------------------------------------------------------------------
// prep: split x lower half into bf16 hi/lo
// ---------------------------------------------------------------------------
__global__ void prep_x_kernel(const float* __restrict__ x,
                              __nv_bfloat16* __restrict__ hi,
                              __nv_bfloat16* __restrict__ lo, int total)
{
    int idx = blockIdx.x * blockDim.x + threadIdx.x;
    if (idx >= total) return;
    int b = idx >> 6, j = idx & 63;
    float v = x[(size_t)b * 128 + j];
    __nv_bfloat16 h = __float2bfloat16(v);
    hi[idx] = h;
    lo[idx] = __float2bfloat16(v - __bfloat162float(h));
}

// ---------------------------------------------------------------------------
// W [K,N] fp32 row-major -> Wt [Npad,K] bf16 hi/lo, tiled SMEM transpose.
// ---------------------------------------------------------------------------
__global__ __launch_bounds__(256)
void conv_w_kernel(const float* __restrict__ W, int K, int N, int Npad,
                   __nv_bfloat16* __restrict__ hi,
                   __nv_bfloat16* __restrict__ lo)
{
    __shared__ float t[32][33];
    const int n0 = blockIdx.x * 32;
    const int k0 = blockIdx.y * 32;
    const int tx = threadIdx.x, ty = threadIdx.y;

    const int n = n0 + tx;
#pragma unroll
    for (int i = 0; i < 32; i += 8) {
        const int k = k0 + ty + i;
        t[ty + i][tx] = (n < N) ? W[(size_t)k * N + n] : 0.f;
    }
    __syncthreads();

#pragma unroll
    for (int i = 0; i < 32; i += 8) {
        const int nn = n0 + ty + i;
        const int kk = k0 + tx;
        const float v = t[tx][ty + i];
        const __nv_bfloat16 h = __float2bfloat16(v);
        hi[(size_t)nn * K + kk] = h;
        lo[(size_t)nn * K + kk] = __float2bfloat16(v - __bfloat162float(h));
    }
}

// ---------------------------------------------------------------------------
// RQS spline + logdet. Coalesced SMEM-staged parameter loads.
// ---------------------------------------------------------------------------
__device__ __forceinline__ float softplusf(float v)
{
    return (v > 20.f) ? v : log1pf(expf(v));
}

__global__ __launch_bounds__(64)
void rqs_kernel(const float* __restrict__ x,
                const float* __restrict__ params,
                __nv_bfloat16* __restrict__ up_hi,
                __nv_bfloat16* __restrict__ up_lo,
                float* __restrict__ dout,
                float* __restrict__ ld_buf,
                int phase, int Bn)
{
    const int b = blockIdx.x;
    const int j = threadIdx.x;  // 0..63

    __shared__ __align__(16) float sp[PDIM];
    {
        const float4* src = reinterpret_cast<const float4*>(
            params + (size_t)b * PDIM);
        float4* dst = reinterpret_cast<float4*>(sp);
#pragma unroll
        for (int i = 0; i < 6; i++) {
            const int q = i * 64 + j;
            if (q < PDIM / 4) dst[q] = src[q];
        }
    }
    const float xv = x[(size_t)b * 128 + (phase == 0 ? 64 + j : j)];
    __syncthreads();

    const float* p = sp + j * 23;  // stride 23: gcd(23,32)=1 -> conflict-free

    float W[8], H[8], D7[7];
#pragma unroll
    for (int i = 0; i < 8; i++) W[i] = p[i];
#pragma unroll
    for (int i = 0; i < 8; i++) H[i] = p[8 + i];
#pragma unroll
    for (int i = 0; i < 7; i++) D7[i] = p[16 + i];

    float mw = W[0];
#pragma unroll
    for (int i = 1; i < 8; i++) mw = fmaxf(mw, W[i]);
    float sw = 0.f;
#pragma unroll
    for (int i = 0; i < 8; i++) { W[i] = expf(W[i] - mw); sw += W[i]; }
    const float invw = 1.f / sw;

    float mh = H[0];
#pragma unroll
    for (int i = 1; i < 8; i++) mh = fmaxf(mh, H[i]);
    float sh = 0.f;
#pragma unroll
    for (int i = 0; i < 8; i++) { H[i] = expf(H[i] - mh); sh += H[i]; }
    const float invh = 1.f / sh;

    float cumw[9], cumh[9];
    cumw[0] = 0.f; cumh[0] = 0.f;
#pragma unroll
    for (int i = 0; i < 8; i++) {
        cumw[i + 1] = cumw[i] + (0.001f + 0.992f * W[i] * invw);
        cumh[i + 1] = cumh[i] + (0.001f + 0.992f * H[i] * invh);
    }
#pragma unroll
    for (int i = 0; i < 9; i++) {
        cumw[i] = 2.f * cumw[i] - 1.f;
        cumh[i] = 2.f * cumh[i] - 1.f;
    }
    cumw[0] = -1.f; cumw[8] = 1.f;
    cumh[0] = -1.f; cumh[8] = 1.f;

    float d[9];
    const float CST = logf(expf(1.0f - 0.001f) - 1.0f);
    const float dpad = 0.001f + softplusf(CST);
    d[0] = dpad; d[8] = dpad;
#pragma unroll
    for (int i = 0; i < 7; i++) d[i + 1] = 0.001f + softplusf(D7[i]);

    int idx = 0;
#pragma unroll
    for (int i = 0; i < 9; i++) {
        float loc = cumw[i] + ((i == 8) ? 1e-6f : 0.f);
        idx += (xv >= loc) ? 1 : 0;
    }
    idx -= 1;
    idx = max(0, min(7, idx));

    float icw = 0.f, iw = 1.f, ich = 0.f, ih = 1.f, d0 = 1.f, d1 = 1.f;
#pragma unroll
    for (int i = 0; i < 8; i++) {
        if (i == idx) {
            icw = cumw[i]; iw = cumw[i + 1] - cumw[i];
            ich = cumh[i]; ih = cumh[i + 1] - cumh[i];
            d0 = d[i]; d1 = d[i + 1];
        }
    }
    const float idel = ih / iw;
    const float th   = (xv - icw) / iw;
    const float omt  = 1.f - th;
    const float t1mt = th * omt;

    const float numer = ih * (idel * th * th + d0 * t1mt);
    const float den   = idel + (d0 + d1 - 2.f * idel) * t1mt;
    float out = ich + numer / den;

    const float dnum = idel * idel *
        (d1 * th * th + 2.f * idel * t1mt + d0 * omt * omt);
    float lad = logf(dnum) - 2.f * logf(den);

    const bool inside = (xv >= -1.f) && (xv <= 1.f);
    if (!inside) { out = xv; lad = 0.f; }

    if (phase == 0) {
        dout[(size_t)b * 128 + 64 + j] = out;
        __nv_bfloat16 h = __float2bfloat16(out);
        up_hi[(size_t)b * 64 + j] = h;
        up_lo[(size_t)b * 64 + j] = __float2bfloat16(out - __bfloat162float(h));
    } else {
        dout[(size_t)b * 128 + j] = out;
    }

    float v = lad;
#pragma unroll
    for (int off = 16; off > 0; off >>= 1)
        v += __shfl_down_sync(0xffffffffu, v, off);
    __shared__ float sred[2];
    if ((j & 31) == 0) sred[j >> 5] = v;
    __syncthreads();
    if (j == 0) {
        const float tot = sred[0] + sred[1];
        if (phase == 0) ld_buf[b] = tot;
        else dout[(size_t)Bn * 128 + b] = ld_buf[b] + tot;
    }
}

// ---------------------------------------------------------------------------
// Launch
// ---------------------------------------------------------------------------
extern "C" void kernel_launch(void* const* d_in, const int* in_sizes, int n_in,
                              void* d_out, int out_size)
{
    const float* x    = (const float*)d_in[0];
    const float* f1w1 = (const float*)d_in[1];
    const float* f1b1 = (const float*)d_in[2];
    const float* f1w2 = (const float*)d_in[3];
    const float* f1b2 = (const float*)d_in[4];
    const float* f1w3 = (const float*)d_in[5];
    const float* f1b3 = (const float*)d_in[6];
    const float* f2w1 = (const float*)d_in[7];
    const float* f2b1 = (const float*)d_in[8];
    const float* f2w2 = (const float*)d_in[9];
    const float* f2b2 = (const float*)d_in[10];
    const float* f2w3 = (const float*)d_in[11];
    const float* f2b3 = (const float*)d_in[12];
    float* out = (float*)d_out;

    const int B = in_sizes[0] / 128;

    __nv_bfloat16 *xlh, *xll, *uph, *upl, *hAh, *hAl, *hBh, *hBl;
    __nv_bfloat16 *w1h, *w1l, *w2h, *w2l, *w3h, *w3l;
    float *pa, *ld;
    cudaGetSymbolAddress((void**)&xlh, g_xl_hi);
    cudaGetSymbolAddress((void**)&xll, g_xl_lo);
    cudaGetSymbolAddress((void**)&uph, g_up_hi);
    cudaGetSymbolAddress((void**)&upl, g_up_lo);
    cudaGetSymbolAddress((void**)&hAh, g_hA_hi);
    cudaGetSymbolAddress((void**)&hAl, g_hA_lo);
    cudaGetSymbolAddress((void**)&hBh, g_hB_hi);
    cudaGetSymbolAddress((void**)&hBl, g_hB_lo);
    cudaGetSymbolAddress((void**)&w1h, g_w1t_hi);
    cudaGetSymbolAddress((void**)&w1l, g_w1t_lo);
    cudaGetSymbolAddress((void**)&w2h, g_w2t_hi);
    cudaGetSymbolAddress((void**)&w2l, g_w2t_lo);
    cudaGetSymbolAddress((void**)&w3h, g_w3t_hi);
    cudaGetSymbolAddress((void**)&w3l, g_w3t_lo);
    cudaGetSymbolAddress((void**)&pa, g_params);
    cudaGetSymbolAddress((void**)&ld, g_ld);

    const int DSMEM = 3 * STAGE_BYTES;  // 96 KB
    cudaFuncSetAttribute((const void*)gemm_hmma<1, 1>,
                         cudaFuncAttributeMaxDynamicSharedMemorySize, DSMEM);
    cudaFuncSetAttribute((const void*)gemm_hmma<0, 0>,
                         cudaFuncAttributeMaxDynamicSharedMemorySize, DSMEM);

    const int MB = B / 128;

    prep_x_kernel<<<(B * 64 + 255) / 256, 256>>>(x, xlh, xll, B * 64);

    // ---- FCNN1 ----
    conv_w_kernel<<<dim3(512 / 32, 64 / 32), dim3(32, 8)>>>(f1w1, 64, 512, 512, w1h, w1l);
    conv_w_kernel<<<dim3(512 / 32, 512 / 32), dim3(32, 8)>>>(f1w2, 512, 512, 512, w2h, w2l);
    conv_w_kernel<<<dim3(PPAD / 32, 512 / 32), dim3(32, 8)>>>(f1w3, 512, PDIM, PPAD, w3h, w3l);

    gemm_hmma<1, 1><<<dim3(4, MB), 512, DSMEM>>>(xlh, xll, 64, w1h, w1l, f1b1,
                                                 nullptr, hAh, hAl, 512, 64);
    gemm_hmma<1, 1><<<dim3(4, MB), 512, DSMEM>>>(hAh, hAl, 512, w2h, w2l, f1b2,
                                                 nullptr, hBh, hBl, 512, 512);
    gemm_hmma<0, 0><<<dim3(PPAD / 128, MB), 512, DSMEM>>>(hBh, hBl, 512, w3h, w3l,
                                                          f1b3, pa, nullptr, nullptr,
                                                          PDIM, 512);

    rqs_kernel<<<B, 64>>>(x, pa, uph, upl, out, ld, 0, B);

    // ---- FCNN2 (reuse weight buffers) ----
    conv_w_kernel<<<dim3(512 / 32, 64 / 32), dim3(32, 8)>>>(f2w1, 64, 512, 512, w1h, w1l);
    conv_w_kernel<<<dim3(512 / 32, 512 / 32), dim3(32, 8)>>>(f2w2, 512, 512, 512, w2h, w2l);
    conv_w_kernel<<<dim3(PPAD / 32, 512 / 32), dim3(32, 8)>>>(f2w3, 512, PDIM, PPAD, w3h, w3l);

    gemm_hmma<1, 1><<<dim3(4, MB), 512, DSMEM>>>(uph, upl, 64, w1h, w1l, f2b1,
                                                 nullptr, hAh, hAl, 512, 64);
    gemm_hmma<1, 1><<<dim3(4, MB), 512, DSMEM>>>(hAh, hAl, 512, w2h, w2l, f2b2,
                                                 nullptr, hBh, hBl, 512, 512);
    gemm_hmma<0, 0><<<dim3(PPAD / 128, MB), 512, DSMEM>>>(hBh, hBl, 512, w3h, w3l,
                                                          f2b3, pa, nullptr, nullptr,
                                                          PDIM, 512);

    rqs_kernel<<<B, 64>>>(x, pa, nullptr, nullptr, out, ld, 1, B);
}

// round 8
// speedup vs baseline: 2.2154x; 2.2154x over previous
#include <cuda_runtime.h>
#include <cuda_fp16.h>
#include <math.h>
#include <stdint.h>

// ---------------------------------------------------------------------------
// NSF coupling layer on GB300 (compute_103-safe tensor path).
//   GEMMs via mma.sync.m16n8k16.f32.f16.f16.f32 — SINGLE-term fp16 operands
//   (fp16 RN error 2^-11 keeps end-to-end rel_err ~5e-4 < 1e-3 threshold).
//   CTA 128x128, BK=32, 8 warps (warp tile 64x32), 3-stage cp.async,
//   2 CTAs/SM (small smem + regs), XOR-swizzled ldmatrix.
// ---------------------------------------------------------------------------

#define MAXB 32768
#define HD   512
#define PDIM 1472
#define PPAD 1536

// ------------------------- scratch (device globals) ------------------------
__device__ __align__(128) __half g_xl[(size_t)MAXB * 64];
__device__ __align__(128) __half g_up[(size_t)MAXB * 64];
__device__ __align__(128) __half g_hA[(size_t)MAXB * HD];
__device__ __align__(128) __half g_hB[(size_t)MAXB * HD];
__device__ __align__(128) float g_params[(size_t)MAXB * PDIM];
__device__ __align__(128) float g_ld[MAXB];
__device__ __align__(128) __half g_w1t[512 * 64];
__device__ __align__(128) __half g_w2t[512 * 512];
__device__ __align__(128) __half g_w3t[PPAD * 512];

// ------------------------- low-level helpers -------------------------------
__device__ __forceinline__ uint32_t smem_u32(const void* p) {
    uint32_t a;
    asm("{ .reg .u64 t; cvta.to.shared.u64 t, %1; cvt.u32.u64 %0, t; }"
        : "=r"(a) : "l"(p));
    return a;
}

__device__ __forceinline__ void ldsm4(uint32_t* r, uint32_t addr) {
    asm volatile("ldmatrix.sync.aligned.m8n8.x4.shared.b16 {%0,%1,%2,%3}, [%4];"
                 : "=r"(r[0]), "=r"(r[1]), "=r"(r[2]), "=r"(r[3]) : "r"(addr));
}

__device__ __forceinline__ void mma16816(float* c, const uint32_t* a,
                                         const uint32_t* b) {
    asm volatile(
        "mma.sync.aligned.m16n8k16.row.col.f32.f16.f16.f32 "
        "{%0,%1,%2,%3}, {%4,%5,%6,%7}, {%8,%9}, {%0,%1,%2,%3};"
        : "+f"(c[0]), "+f"(c[1]), "+f"(c[2]), "+f"(c[3])
        : "r"(a[0]), "r"(a[1]), "r"(a[2]), "r"(a[3]), "r"(b[0]), "r"(b[1]));
}

#define CP_ASYNC16(sa, gp) \
    asm volatile("cp.async.cg.shared.global [%0], [%1], 16;" :: "r"(sa), "l"(gp))
#define CP_COMMIT() asm volatile("cp.async.commit_group;" ::: "memory")
#define CP_WAIT1()  asm volatile("cp.async.wait_group 1;" ::: "memory")

// ---------------------------------------------------------------------------
// HMMA GEMM:  C[M, Nreal] = A[M,K] @ Wt[Npad,K]^T + bias  (opt SiLU)
// CTA 128x128, BK=32, 8 warps (2 M x 4 N), warp tile 64x32, fp16 operands.
// SMEM tile per matrix: 128 rows x 32 fp16 (64 B/row), XOR-swizzled:
//   phys = row*64 + ((chunk ^ ((row>>1)&3)) << 4)
// Stage = {A, B} = 2 * 8KB = 16KB; three stages = 48KB; 2 CTAs/SM.
// ---------------------------------------------------------------------------
#define STAGE_BYTES 16384

__device__ __forceinline__ void load_stage(
    uint32_t sbase,
    const __half* a, const __half* b,
    int lda, int ldb, int tid)
{
#pragma unroll
    for (int it = 0; it < 4; it++) {
        const int idx = it * 256 + tid;
        const int mat = idx >> 9;         // 0 = A, 1 = B
        const int cid = idx & 511;
        const int row = cid >> 2;
        const int ch  = cid & 3;
        const int ld  = (mat == 0) ? lda : ldb;
        const __half* g = (mat == 0) ? a : b;
        const void* gp = g + (size_t)row * ld + ch * 8;
        const uint32_t sa =
            sbase + mat * 8192 + row * 64 + ((ch ^ ((row >> 1) & 3)) << 4);
        CP_ASYNC16(sa, gp);
    }
}

template <int ACT, int SPLIT>
__global__ __launch_bounds__(256, 2)
void gemm_hmma(const __half* __restrict__ A, int lda,
               const __half* __restrict__ B,
               const float* __restrict__ bias,
               float* __restrict__ outf,
               __half* __restrict__ oh,
               int Nreal, int K)
{
    extern __shared__ char smem[];
    const uint32_t sbase = smem_u32(smem);

    const int tid  = threadIdx.x;
    const int lane = tid & 31;
    const int wid  = tid >> 5;
    const int warp_m = (wid >> 2) * 64;   // 0 or 64
    const int warp_n = (wid & 3) * 32;    // 0,32,64,96
    const int m0 = blockIdx.y * 128;
    const int n0 = blockIdx.x * 128;

    const __half* Ap = A + (size_t)m0 * lda;
    const __half* Bp = B + (size_t)n0 * K;

    float acc[4][4][4];
#pragma unroll
    for (int i = 0; i < 4; i++)
#pragma unroll
        for (int j = 0; j < 4; j++)
#pragma unroll
            for (int q = 0; q < 4; q++) acc[i][j][q] = 0.f;

    const int nk = K >> 5;  // BK = 32

    // prologue: prefetch stages 0 and 1 (each its own commit group)
    load_stage(sbase, Ap, Bp, lda, K, tid);
    CP_COMMIT();
    if (nk > 1) {
        load_stage(sbase + STAGE_BYTES, Ap + 32, Bp + 32, lda, K, tid);
    }
    CP_COMMIT();

    int buf = 0;
    for (int kc = 0; kc < nk; kc++) {
        CP_WAIT1();           // stage kc arrived (<=1 group in flight)
        __syncthreads();      // visibility + all warps done with prev buf

        if (kc + 2 < nk) {
            const int ko = (kc + 2) * 32;
            int nbuf = buf + 2; if (nbuf >= 3) nbuf -= 3;
            load_stage(sbase + nbuf * STAGE_BYTES, Ap + ko, Bp + ko, lda, K, tid);
        }
        CP_COMMIT();          // keep group-count invariant

        const uint32_t st = sbase + buf * STAGE_BYTES;
        const uint32_t aB = st, bB = st + 8192;

#pragma unroll
        for (int s = 0; s < 2; s++) {  // two k16 steps per chunk
            uint32_t ah[4][4];
            const int chA = s * 2 + (lane >> 4);
#pragma unroll
            for (int i = 0; i < 4; i++) {
                const int r = warp_m + i * 16 + (lane & 15);
                const uint32_t off = r * 64 + ((chA ^ ((r >> 1) & 3)) << 4);
                ldsm4(ah[i], aB + off);
            }
            uint32_t bh[2][4];
            const int chB = s * 2 + ((lane >> 3) & 1);
#pragma unroll
            for (int j2 = 0; j2 < 2; j2++) {
                const int n = warp_n + j2 * 16 + (lane & 7) + ((lane >> 4) << 3);
                const uint32_t off = n * 64 + ((chB ^ ((n >> 1) & 3)) << 4);
                ldsm4(bh[j2], bB + off);
            }
#pragma unroll
            for (int i = 0; i < 4; i++)
#pragma unroll
                for (int j = 0; j < 4; j++)
                    mma16816(acc[i][j], ah[i], &bh[j >> 1][(j & 1) * 2]);
        }
        buf++; if (buf == 3) buf = 0;
    }

    // ---- epilogue: bias + opt SiLU + store (fp32 or fp16) ----
#pragma unroll
    for (int i = 0; i < 4; i++) {
        const int r0 = m0 + warp_m + i * 16 + (lane >> 2);
#pragma unroll
        for (int j = 0; j < 4; j++) {
            const int col = n0 + warp_n + j * 8 + ((lane & 3) << 1);
            if (col < Nreal) {
                const float b0 = bias[col];
                const float b1 = bias[col + 1];
#pragma unroll
                for (int h = 0; h < 2; h++) {
                    const int r = r0 + h * 8;
                    float v0 = acc[i][j][h * 2 + 0] + b0;
                    float v1 = acc[i][j][h * 2 + 1] + b1;
                    if (ACT) {
                        v0 = v0 / (1.f + __expf(-v0));
                        v1 = v1 / (1.f + __expf(-v1));
                    }
                    const size_t ob = (size_t)r * Nreal + col;
                    if (SPLIT) {
                        *reinterpret_cast<__half2*>(oh + ob) =
                            __halves2half2(__float2half(v0), __float2half(v1));
                    } else {
                        float2 v; v.x = v0; v.y = v1;
                        *reinterpret_cast<float2*>(outf + ob) = v;
                    }
                }
            }
        }
    }
}

// ---------------------------------------------------------------------------
// prep: x lower half -> fp16
// ---------------------------------------------------------------------------
__global__ void prep_x_kernel(const float* __restrict__ x,
                              __half* __restrict__ hx, int total)
{
    int idx = blockIdx.x * blockDim.x + threadIdx.x;
    if (idx >= total) return;
    int b = idx >> 6, j = idx & 63;
    hx[idx] = __float2half(x[(size_t)b * 128 + j]);
}

// ---------------------------------------------------------------------------
// W [K,N] fp32 row-major -> Wt [Npad,K] fp16 transposed (zero-padded).
// ---------------------------------------------------------------------------
__global__ __launch_bounds__(256)
void conv_w_kernel(const float* __restrict__ W, int K, int N, int Npad,
                   __half* __restrict__ Wt)
{
    __shared__ float t[32][33];
    const int n0 = blockIdx.x * 32;
    const int k0 = blockIdx.y * 32;
    const int tx = threadIdx.x, ty = threadIdx.y;

    const int n = n0 + tx;
#pragma unroll
    for (int i = 0; i < 32; i += 8) {
        const int k = k0 + ty + i;
        t[ty + i][tx] = (n < N) ? W[(size_t)k * N + n] : 0.f;
    }
    __syncthreads();

#pragma unroll
    for (int i = 0; i < 32; i += 8) {
        const int nn = n0 + ty + i;
        const int kk = k0 + tx;
        Wt[(size_t)nn * K + kk] = __float2half(t[tx][ty + i]);
    }
}

// ---------------------------------------------------------------------------
// RQS spline + logdet. Coalesced SMEM-staged parameter loads.
// ---------------------------------------------------------------------------
__device__ __forceinline__ float softplusf(float v)
{
    return (v > 20.f) ? v : log1pf(expf(v));
}

__global__ __launch_bounds__(64)
void rqs_kernel(const float* __restrict__ x,
                const float* __restrict__ params,
                __half* __restrict__ up,
                float* __restrict__ dout,
                float* __restrict__ ld_buf,
                int phase, int Bn)
{
    const int b = blockIdx.x;
    const int j = threadIdx.x;  // 0..63

    __shared__ __align__(16) float sp[PDIM];
    {
        const float4* src = reinterpret_cast<const float4*>(
            params + (size_t)b * PDIM);
        float4* dst = reinterpret_cast<float4*>(sp);
#pragma unroll
        for (int i = 0; i < 6; i++) {
            const int q = i * 64 + j;
            if (q < PDIM / 4) dst[q] = src[q];
        }
    }
    const float xv = x[(size_t)b * 128 + (phase == 0 ? 64 + j : j)];
    __syncthreads();

    const float* p = sp + j * 23;  // stride 23: conflict-free

    float W[8], H[8], D7[7];
#pragma unroll
    for (int i = 0; i < 8; i++) W[i] = p[i];
#pragma unroll
    for (int i = 0; i < 8; i++) H[i] = p[8 + i];
#pragma unroll
    for (int i = 0; i < 7; i++) D7[i] = p[16 + i];

    float mw = W[0];
#pragma unroll
    for (int i = 1; i < 8; i++) mw = fmaxf(mw, W[i]);
    float sw = 0.f;
#pragma unroll
    for (int i = 0; i < 8; i++) { W[i] = expf(W[i] - mw); sw += W[i]; }
    const float invw = 1.f / sw;

    float mh = H[0];
#pragma unroll
    for (int i = 1; i < 8; i++) mh = fmaxf(mh, H[i]);
    float sh = 0.f;
#pragma unroll
    for (int i = 0; i < 8; i++) { H[i] = expf(H[i] - mh); sh += H[i]; }
    const float invh = 1.f / sh;

    float cumw[9], cumh[9];
    cumw[0] = 0.f; cumh[0] = 0.f;
#pragma unroll
    for (int i = 0; i < 8; i++) {
        cumw[i + 1] = cumw[i] + (0.001f + 0.992f * W[i] * invw);
        cumh[i + 1] = cumh[i] + (0.001f + 0.992f * H[i] * invh);
    }
#pragma unroll
    for (int i = 0; i < 9; i++) {
        cumw[i] = 2.f * cumw[i] - 1.f;
        cumh[i] = 2.f * cumh[i] - 1.f;
    }
    cumw[0] = -1.f; cumw[8] = 1.f;
    cumh[0] = -1.f; cumh[8] = 1.f;

    float d[9];
    const float CST = logf(expf(1.0f - 0.001f) - 1.0f);
    const float dpad = 0.001f + softplusf(CST);
    d[0] = dpad; d[8] = dpad;
#pragma unroll
    for (int i = 0; i < 7; i++) d[i + 1] = 0.001f + softplusf(D7[i]);

    int idx = 0;
#pragma unroll
    for (int i = 0; i < 9; i++) {
        float loc = cumw[i] + ((i == 8) ? 1e-6f : 0.f);
        idx += (xv >= loc) ? 1 : 0;
    }
    idx -= 1;
    idx = max(0, min(7, idx));

    float icw = 0.f, iw = 1.f, ich = 0.f, ih = 1.f, d0 = 1.f, d1 = 1.f;
#pragma unroll
    for (int i = 0; i < 8; i++) {
        if (i == idx) {
            icw = cumw[i]; iw = cumw[i + 1] - cumw[i];
            ich = cumh[i]; ih = cumh[i + 1] - cumh[i];
            d0 = d[i]; d1 = d[i + 1];
        }
    }
    const float idel = ih / iw;
    const float th   = (xv - icw) / iw;
    const float omt  = 1.f - th;
    const float t1mt = th * omt;

    const float numer = ih * (idel * th * th + d0 * t1mt);
    const float den   = idel + (d0 + d1 - 2.f * idel) * t1mt;
    float out = ich + numer / den;

    const float dnum = idel * idel *
        (d1 * th * th + 2.f * idel * t1mt + d0 * omt * omt);
    float lad = logf(dnum) - 2.f * logf(den);

    const bool inside = (xv >= -1.f) && (xv <= 1.f);
    if (!inside) { out = xv; lad = 0.f; }

    if (phase == 0) {
        dout[(size_t)b * 128 + 64 + j] = out;
        up[(size_t)b * 64 + j] = __float2half(out);
    } else {
        dout[(size_t)b * 128 + j] = out;
    }

    float v = lad;
#pragma unroll
    for (int off = 16; off > 0; off >>= 1)
        v += __shfl_down_sync(0xffffffffu, v, off);
    __shared__ float sred[2];
    if ((j & 31) == 0) sred[j >> 5] = v;
    __syncthreads();
    if (j == 0) {
        const float tot = sred[0] + sred[1];
        if (phase == 0) ld_buf[b] = tot;
        else dout[(size_t)Bn * 128 + b] = ld_buf[b] + tot;
    }
}

// ---------------------------------------------------------------------------
// Launch
// ---------------------------------------------------------------------------
extern "C" void kernel_launch(void* const* d_in, const int* in_sizes, int n_in,
                              void* d_out, int out_size)
{
    const float* x    = (const float*)d_in[0];
    const float* f1w1 = (const float*)d_in[1];
    const float* f1b1 = (const float*)d_in[2];
    const float* f1w2 = (const float*)d_in[3];
    const float* f1b2 = (const float*)d_in[4];
    const float* f1w3 = (const float*)d_in[5];
    const float* f1b3 = (const float*)d_in[6];
    const float* f2w1 = (const float*)d_in[7];
    const float* f2b1 = (const float*)d_in[8];
    const float* f2w2 = (const float*)d_in[9];
    const float* f2b2 = (const float*)d_in[10];
    const float* f2w3 = (const float*)d_in[11];
    const float* f2b3 = (const float*)d_in[12];
    float* out = (float*)d_out;

    const int B = in_sizes[0] / 128;

    __half *xl, *up, *hA, *hB, *w1, *w2, *w3;
    float *pa, *ld;
    cudaGetSymbolAddress((void**)&xl, g_xl);
    cudaGetSymbolAddress((void**)&up, g_up);
    cudaGetSymbolAddress((void**)&hA, g_hA);
    cudaGetSymbolAddress((void**)&hB, g_hB);
    cudaGetSymbolAddress((void**)&w1, g_w1t);
    cudaGetSymbolAddress((void**)&w2, g_w2t);
    cudaGetSymbolAddress((void**)&w3, g_w3t);
    cudaGetSymbolAddress((void**)&pa, g_params);
    cudaGetSymbolAddress((void**)&ld, g_ld);

    const int DSMEM = 3 * STAGE_BYTES;  // 48 KB
    cudaFuncSetAttribute((const void*)gemm_hmma<1, 1>,
                         cudaFuncAttributeMaxDynamicSharedMemorySize, DSMEM);
    cudaFuncSetAttribute((const void*)gemm_hmma<0, 0>,
                         cudaFuncAttributeMaxDynamicSharedMemorySize, DSMEM);

    const int MB = B / 128;

    prep_x_kernel<<<(B * 64 + 255) / 256, 256>>>(x, xl, B * 64);

    // ---- FCNN1 ----
    conv_w_kernel<<<dim3(512 / 32, 64 / 32), dim3(32, 8)>>>(f1w1, 64, 512, 512, w1);
    conv_w_kernel<<<dim3(512 / 32, 512 / 32), dim3(32, 8)>>>(f1w2, 512, 512, 512, w2);
    conv_w_kernel<<<dim3(PPAD / 32, 512 / 32), dim3(32, 8)>>>(f1w3, 512, PDIM, PPAD, w3);

    gemm_hmma<1, 1><<<dim3(4, MB), 256, DSMEM>>>(xl, 64, w1, f1b1,
                                                 nullptr, hA, 512, 64);
    gemm_hmma<1, 1><<<dim3(4, MB), 256, DSMEM>>>(hA, 512, w2, f1b2,
                                                 nullptr, hB, 512, 512);
    gemm_hmma<0, 0><<<dim3(PPAD / 128, MB), 256, DSMEM>>>(hB, 512, w3, f1b3,
                                                          pa, nullptr, PDIM, 512);

    rqs_kernel<<<B, 64>>>(x, pa, up, out, ld, 0, B);

    // ---- FCNN2 (reuse weight buffers) ----
    conv_w_kernel<<<dim3(512 / 32, 64 / 32), dim3(32, 8)>>>(f2w1, 64, 512, 512, w1);
    conv_w_kernel<<<dim3(512 / 32, 512 / 32), dim3(32, 8)>>>(f2w2, 512, 512, 512, w2);
    conv_w_kernel<<<dim3(PPAD / 32, 512 / 32), dim3(32, 8)>>>(f2w3, 512, PDIM, PPAD, w3);

    gemm_hmma<1, 1><<<dim3(4, MB), 256, DSMEM>>>(up, 64, w1, f2b1,
                                                 nullptr, hA, 512, 64);
    gemm_hmma<1, 1><<<dim3(4, MB), 256, DSMEM>>>(hA, 512, w2, f2b2,
                                                 nullptr, hB, 512, 512);
    gemm_hmma<0, 0><<<dim3(PPAD / 128, MB), 256, DSMEM>>>(hB, 512, w3, f2b3,
                                                          pa, nullptr, PDIM, 512);

    rqs_kernel<<<B, 64>>>(x, pa, nullptr, out, ld, 1, B);
}

// round 9
// speedup vs baseline: 2.3604x; 1.0654x over previous
#include <cuda_runtime.h>
#include <cuda_fp16.h>
#include <math.h>
#include <stdint.h>

// ---------------------------------------------------------------------------
// NSF coupling layer on GB300 (compute_103-safe tensor path).
//   GEMMs: mma.sync.m16n8k16.f32.f16.f16.f32, single-term fp16.
//   CTA 128x128, BK=64, 8 warps (warp tile 64x32), 2-stage cp.async
//   double buffer (32KB/stage), 2 CTAs/SM, SW128 swizzle.
// ---------------------------------------------------------------------------

#define MAXB 32768
#define HD   512
#define PDIM 1472
#define PPAD 1536

// ------------------------- scratch (device globals) ------------------------
__device__ __align__(128) __half g_xl[(size_t)MAXB * 64];
__device__ __align__(128) __half g_up[(size_t)MAXB * 64];
__device__ __align__(128) __half g_hA[(size_t)MAXB * HD];
__device__ __align__(128) __half g_hB[(size_t)MAXB * HD];
__device__ __align__(128) float g_params[(size_t)MAXB * PDIM];
__device__ __align__(128) float g_ld[MAXB];
__device__ __align__(128) __half g_w1t[512 * 64];
__device__ __align__(128) __half g_w2t[512 * 512];
__device__ __align__(128) __half g_w3t[PPAD * 512];

// ------------------------- low-level helpers -------------------------------
__device__ __forceinline__ uint32_t smem_u32(const void* p) {
    uint32_t a;
    asm("{ .reg .u64 t; cvta.to.shared.u64 t, %1; cvt.u32.u64 %0, t; }"
        : "=r"(a) : "l"(p));
    return a;
}

__device__ __forceinline__ void ldsm4(uint32_t* r, uint32_t addr) {
    asm volatile("ldmatrix.sync.aligned.m8n8.x4.shared.b16 {%0,%1,%2,%3}, [%4];"
                 : "=r"(r[0]), "=r"(r[1]), "=r"(r[2]), "=r"(r[3]) : "r"(addr));
}

__device__ __forceinline__ void mma16816(float* c, const uint32_t* a,
                                         const uint32_t* b) {
    asm volatile(
        "mma.sync.aligned.m16n8k16.row.col.f32.f16.f16.f32 "
        "{%0,%1,%2,%3}, {%4,%5,%6,%7}, {%8,%9}, {%0,%1,%2,%3};"
        : "+f"(c[0]), "+f"(c[1]), "+f"(c[2]), "+f"(c[3])
        : "r"(a[0]), "r"(a[1]), "r"(a[2]), "r"(a[3]), "r"(b[0]), "r"(b[1]));
}

#define CP_ASYNC16(sa, gp) \
    asm volatile("cp.async.cg.shared.global [%0], [%1], 16;" :: "r"(sa), "l"(gp))
#define CP_COMMIT() asm volatile("cp.async.commit_group;" ::: "memory")
#define CP_WAIT0()  asm volatile("cp.async.wait_group 0;" ::: "memory")

// ---------------------------------------------------------------------------
// HMMA GEMM:  C[M, Nreal] = A[M,K] @ Wt[Npad,K]^T + bias  (opt SiLU)
// CTA 128x128, BK=64, 8 warps (2 M x 4 N), warp tile 64x32, fp16 operands.
// SMEM tile per matrix: 128 rows x 64 fp16 (128 B/row), SW128 swizzle:
//   phys = row*128 + ((chunk16 ^ (row & 7)) << 4)
// Stage = {A, B} = 2 * 16KB = 32KB; two stages = 64KB; 2 CTAs/SM.
// ---------------------------------------------------------------------------
#define STAGE_BYTES 32768

__device__ __forceinline__ void load_stage(
    uint32_t sbase,
    const __half* a, const __half* b,
    int lda, int ldb, int tid)
{
#pragma unroll
    for (int it = 0; it < 8; it++) {
        const int idx = it * 256 + tid;
        const int mat = idx >> 10;        // 0 = A, 1 = B
        const int cid = idx & 1023;
        const int row = cid >> 3;
        const int ch  = cid & 7;
        const int ld  = (mat == 0) ? lda : ldb;
        const __half* g = (mat == 0) ? a : b;
        const void* gp = g + (size_t)row * ld + ch * 8;
        const uint32_t sa =
            sbase + mat * 16384 + row * 128 + ((ch ^ (row & 7)) << 4);
        CP_ASYNC16(sa, gp);
    }
}

template <int ACT, int SPLIT>
__global__ __launch_bounds__(256, 2)
void gemm_hmma(const __half* __restrict__ A, int lda,
               const __half* __restrict__ B,
               const float* __restrict__ bias,
               float* __restrict__ outf,
               __half* __restrict__ oh,
               int Nreal, int K)
{
    extern __shared__ char smem[];
    const uint32_t sbase = smem_u32(smem);

    const int tid  = threadIdx.x;
    const int lane = tid & 31;
    const int wid  = tid >> 5;
    const int warp_m = (wid >> 2) * 64;   // 0 or 64
    const int warp_n = (wid & 3) * 32;    // 0,32,64,96
    const int m0 = blockIdx.y * 128;
    const int n0 = blockIdx.x * 128;

    const __half* Ap = A + (size_t)m0 * lda;
    const __half* Bp = B + (size_t)n0 * K;

    float acc[4][4][4];
#pragma unroll
    for (int i = 0; i < 4; i++)
#pragma unroll
        for (int j = 0; j < 4; j++)
#pragma unroll
            for (int q = 0; q < 4; q++) acc[i][j][q] = 0.f;

    const int nk = K >> 6;  // BK = 64

    // prologue: prefetch stage 0
    load_stage(sbase, Ap, Bp, lda, K, tid);
    CP_COMMIT();

    for (int kc = 0; kc < nk; kc++) {
        CP_WAIT0();           // stage kc arrived
        __syncthreads();      // all warps done reading the other buffer

        if (kc + 1 < nk) {    // prefetch next chunk into other buffer
            const int ko = (kc + 1) * 64;
            load_stage(sbase + ((kc + 1) & 1) * STAGE_BYTES,
                       Ap + ko, Bp + ko, lda, K, tid);
            CP_COMMIT();
        }

        const uint32_t st = sbase + (kc & 1) * STAGE_BYTES;
        const uint32_t aB = st, bB = st + 16384;

#pragma unroll
        for (int s = 0; s < 4; s++) {  // four k16 steps per chunk
            uint32_t ah[4][4];
            const int chA = s * 2 + (lane >> 4);
#pragma unroll
            for (int i = 0; i < 4; i++) {
                const int r = warp_m + i * 16 + (lane & 15);
                const uint32_t off = r * 128 + ((chA ^ (r & 7)) << 4);
                ldsm4(ah[i], aB + off);
            }
            uint32_t bh[2][4];
            const int chB = s * 2 + ((lane >> 3) & 1);
#pragma unroll
            for (int j2 = 0; j2 < 2; j2++) {
                const int n = warp_n + j2 * 16 + (lane & 7) + ((lane >> 4) << 3);
                const uint32_t off = n * 128 + ((chB ^ (n & 7)) << 4);
                ldsm4(bh[j2], bB + off);
            }
#pragma unroll
            for (int i = 0; i < 4; i++)
#pragma unroll
                for (int j = 0; j < 4; j++)
                    mma16816(acc[i][j], ah[i], &bh[j >> 1][(j & 1) * 2]);
        }
        // next iteration's __syncthreads() guards the buffer swap
    }

    // ---- epilogue: bias + opt SiLU + store (fp32 or fp16) ----
#pragma unroll
    for (int i = 0; i < 4; i++) {
        const int r0 = m0 + warp_m + i * 16 + (lane >> 2);
#pragma unroll
        for (int j = 0; j < 4; j++) {
            const int col = n0 + warp_n + j * 8 + ((lane & 3) << 1);
            if (col < Nreal) {
                const float b0 = bias[col];
                const float b1 = bias[col + 1];
#pragma unroll
                for (int h = 0; h < 2; h++) {
                    const int r = r0 + h * 8;
                    float v0 = acc[i][j][h * 2 + 0] + b0;
                    float v1 = acc[i][j][h * 2 + 1] + b1;
                    if (ACT) {
                        v0 = v0 / (1.f + __expf(-v0));
                        v1 = v1 / (1.f + __expf(-v1));
                    }
                    const size_t ob = (size_t)r * Nreal + col;
                    if (SPLIT) {
                        *reinterpret_cast<__half2*>(oh + ob) =
                            __halves2half2(__float2half(v0), __float2half(v1));
                    } else {
                        float2 v; v.x = v0; v.y = v1;
                        *reinterpret_cast<float2*>(outf + ob) = v;
                    }
                }
            }
        }
    }
}

// ---------------------------------------------------------------------------
// prep: x lower half -> fp16
// ---------------------------------------------------------------------------
__global__ void prep_x_kernel(const float* __restrict__ x,
                              __half* __restrict__ hx, int total)
{
    int idx = blockIdx.x * blockDim.x + threadIdx.x;
    if (idx >= total) return;
    int b = idx >> 6, j = idx & 63;
    hx[idx] = __float2half(x[(size_t)b * 128 + j]);
}

// ---------------------------------------------------------------------------
// W [K,N] fp32 row-major -> Wt [Npad,K] fp16 transposed (zero-padded).
// ---------------------------------------------------------------------------
__global__ __launch_bounds__(256)
void conv_w_kernel(const float* __restrict__ W, int K, int N, int Npad,
                   __half* __restrict__ Wt)
{
    __shared__ float t[32][33];
    const int n0 = blockIdx.x * 32;
    const int k0 = blockIdx.y * 32;
    const int tx = threadIdx.x, ty = threadIdx.y;

    const int n = n0 + tx;
#pragma unroll
    for (int i = 0; i < 32; i += 8) {
        const int k = k0 + ty + i;
        t[ty + i][tx] = (n < N) ? W[(size_t)k * N + n] : 0.f;
    }
    __syncthreads();

#pragma unroll
    for (int i = 0; i < 32; i += 8) {
        const int nn = n0 + ty + i;
        const int kk = k0 + tx;
        Wt[(size_t)nn * K + kk] = __float2half(t[tx][ty + i]);
    }
}

// ---------------------------------------------------------------------------
// RQS spline + logdet. Coalesced SMEM-staged parameter loads.
// ---------------------------------------------------------------------------
__device__ __forceinline__ float softplusf(float v)
{
    return (v > 20.f) ? v : log1pf(expf(v));
}

__global__ __launch_bounds__(64)
void rqs_kernel(const float* __restrict__ x,
                const float* __restrict__ params,
                __half* __restrict__ up,
                float* __restrict__ dout,
                float* __restrict__ ld_buf,
                int phase, int Bn)
{
    const int b = blockIdx.x;
    const int j = threadIdx.x;  // 0..63

    __shared__ __align__(16) float sp[PDIM];
    {
        const float4* src = reinterpret_cast<const float4*>(
            params + (size_t)b * PDIM);
        float4* dst = reinterpret_cast<float4*>(sp);
#pragma unroll
        for (int i = 0; i < 6; i++) {
            const int q = i * 64 + j;
            if (q < PDIM / 4) dst[q] = src[q];
        }
    }
    const float xv = x[(size_t)b * 128 + (phase == 0 ? 64 + j : j)];
    __syncthreads();

    const float* p = sp + j * 23;  // stride 23: conflict-free

    float W[8], H[8], D7[7];
#pragma unroll
    for (int i = 0; i < 8; i++) W[i] = p[i];
#pragma unroll
    for (int i = 0; i < 8; i++) H[i] = p[8 + i];
#pragma unroll
    for (int i = 0; i < 7; i++) D7[i] = p[16 + i];

    float mw = W[0];
#pragma unroll
    for (int i = 1; i < 8; i++) mw = fmaxf(mw, W[i]);
    float sw = 0.f;
#pragma unroll
    for (int i = 0; i < 8; i++) { W[i] = expf(W[i] - mw); sw += W[i]; }
    const float invw = 1.f / sw;

    float mh = H[0];
#pragma unroll
    for (int i = 1; i < 8; i++) mh = fmaxf(mh, H[i]);
    float sh = 0.f;
#pragma unroll
    for (int i = 0; i < 8; i++) { H[i] = expf(H[i] - mh); sh += H[i]; }
    const float invh = 1.f / sh;

    float cumw[9], cumh[9];
    cumw[0] = 0.f; cumh[0] = 0.f;
#pragma unroll
    for (int i = 0; i < 8; i++) {
        cumw[i + 1] = cumw[i] + (0.001f + 0.992f * W[i] * invw);
        cumh[i + 1] = cumh[i] + (0.001f + 0.992f * H[i] * invh);
    }
#pragma unroll
    for (int i = 0; i < 9; i++) {
        cumw[i] = 2.f * cumw[i] - 1.f;
        cumh[i] = 2.f * cumh[i] - 1.f;
    }
    cumw[0] = -1.f; cumw[8] = 1.f;
    cumh[0] = -1.f; cumh[8] = 1.f;

    float d[9];
    const float CST = logf(expf(1.0f - 0.001f) - 1.0f);
    const float dpad = 0.001f + softplusf(CST);
    d[0] = dpad; d[8] = dpad;
#pragma unroll
    for (int i = 0; i < 7; i++) d[i + 1] = 0.001f + softplusf(D7[i]);

    int idx = 0;
#pragma unroll
    for (int i = 0; i < 9; i++) {
        float loc = cumw[i] + ((i == 8) ? 1e-6f : 0.f);
        idx += (xv >= loc) ? 1 : 0;
    }
    idx -= 1;
    idx = max(0, min(7, idx));

    float icw = 0.f, iw = 1.f, ich = 0.f, ih = 1.f, d0 = 1.f, d1 = 1.f;
#pragma unroll
    for (int i = 0; i < 8; i++) {
        if (i == idx) {
            icw = cumw[i]; iw = cumw[i + 1] - cumw[i];
            ich = cumh[i]; ih = cumh[i + 1] - cumh[i];
            d0 = d[i]; d1 = d[i + 1];
        }
    }
    const float idel = ih / iw;
    const float th   = (xv - icw) / iw;
    const float omt  = 1.f - th;
    const float t1mt = th * omt;

    const float numer = ih * (idel * th * th + d0 * t1mt);
    const float den   = idel + (d0 + d1 - 2.f * idel) * t1mt;
    float out = ich + numer / den;

    const float dnum = idel * idel *
        (d1 * th * th + 2.f * idel * t1mt + d0 * omt * omt);
    float lad = logf(dnum) - 2.f * logf(den);

    const bool inside = (xv >= -1.f) && (xv <= 1.f);
    if (!inside) { out = xv; lad = 0.f; }

    if (phase == 0) {
        dout[(size_t)b * 128 + 64 + j] = out;
        up[(size_t)b * 64 + j] = __float2half(out);
    } else {
        dout[(size_t)b * 128 + j] = out;
    }

    float v = lad;
#pragma unroll
    for (int off = 16; off > 0; off >>= 1)
        v += __shfl_down_sync(0xffffffffu, v, off);
    __shared__ float sred[2];
    if ((j & 31) == 0) sred[j >> 5] = v;
    __syncthreads();
    if (j == 0) {
        const float tot = sred[0] + sred[1];
        if (phase == 0) ld_buf[b] = tot;
        else dout[(size_t)Bn * 128 + b] = ld_buf[b] + tot;
    }
}

// ---------------------------------------------------------------------------
// Launch
// ---------------------------------------------------------------------------
extern "C" void kernel_launch(void* const* d_in, const int* in_sizes, int n_in,
                              void* d_out, int out_size)
{
    const float* x    = (const float*)d_in[0];
    const float* f1w1 = (const float*)d_in[1];
    const float* f1b1 = (const float*)d_in[2];
    const float* f1w2 = (const float*)d_in[3];
    const float* f1b2 = (const float*)d_in[4];
    const float* f1w3 = (const float*)d_in[5];
    const float* f1b3 = (const float*)d_in[6];
    const float* f2w1 = (const float*)d_in[7];
    const float* f2b1 = (const float*)d_in[8];
    const float* f2w2 = (const float*)d_in[9];
    const float* f2b2 = (const float*)d_in[10];
    const float* f2w3 = (const float*)d_in[11];
    const float* f2b3 = (const float*)d_in[12];
    float* out = (float*)d_out;

    const int B = in_sizes[0] / 128;

    __half *xl, *up, *hA, *hB, *w1, *w2, *w3;
    float *pa, *ld;
    cudaGetSymbolAddress((void**)&xl, g_xl);
    cudaGetSymbolAddress((void**)&up, g_up);
    cudaGetSymbolAddress((void**)&hA, g_hA);
    cudaGetSymbolAddress((void**)&hB, g_hB);
    cudaGetSymbolAddress((void**)&w1, g_w1t);
    cudaGetSymbolAddress((void**)&w2, g_w2t);
    cudaGetSymbolAddress((void**)&w3, g_w3t);
    cudaGetSymbolAddress((void**)&pa, g_params);
    cudaGetSymbolAddress((void**)&ld, g_ld);

    const int DSMEM = 2 * STAGE_BYTES;  // 64 KB
    cudaFuncSetAttribute((const void*)gemm_hmma<1, 1>,
                         cudaFuncAttributeMaxDynamicSharedMemorySize, DSMEM);
    cudaFuncSetAttribute((const void*)gemm_hmma<0, 0>,
                         cudaFuncAttributeMaxDynamicSharedMemorySize, DSMEM);

    const int MB = B / 128;

    prep_x_kernel<<<(B * 64 + 255) / 256, 256>>>(x, xl, B * 64);

    // ---- FCNN1 ----
    conv_w_kernel<<<dim3(512 / 32, 64 / 32), dim3(32, 8)>>>(f1w1, 64, 512, 512, w1);
    conv_w_kernel<<<dim3(512 / 32, 512 / 32), dim3(32, 8)>>>(f1w2, 512, 512, 512, w2);
    conv_w_kernel<<<dim3(PPAD / 32, 512 / 32), dim3(32, 8)>>>(f1w3, 512, PDIM, PPAD, w3);

    gemm_hmma<1, 1><<<dim3(4, MB), 256, DSMEM>>>(xl, 64, w1, f1b1,
                                                 nullptr, hA, 512, 64);
    gemm_hmma<1, 1><<<dim3(4, MB), 256, DSMEM>>>(hA, 512, w2, f1b2,
                                                 nullptr, hB, 512, 512);
    gemm_hmma<0, 0><<<dim3(PPAD / 128, MB), 256, DSMEM>>>(hB, 512, w3, f1b3,
                                                          pa, nullptr, PDIM, 512);

    rqs_kernel<<<B, 64>>>(x, pa, up, out, ld, 0, B);

    // ---- FCNN2 (reuse weight buffers) ----
    conv_w_kernel<<<dim3(512 / 32, 64 / 32), dim3(32, 8)>>>(f2w1, 64, 512, 512, w1);
    conv_w_kernel<<<dim3(512 / 32, 512 / 32), dim3(32, 8)>>>(f2w2, 512, 512, 512, w2);
    conv_w_kernel<<<dim3(PPAD / 32, 512 / 32), dim3(32, 8)>>>(f2w3, 512, PDIM, PPAD, w3);

    gemm_hmma<1, 1><<<dim3(4, MB), 256, DSMEM>>>(up, 64, w1, f2b1,
                                                 nullptr, hA, 512, 64);
    gemm_hmma<1, 1><<<dim3(4, MB), 256, DSMEM>>>(hA, 512, w2, f2b2,
                                                 nullptr, hB, 512, 512);
    gemm_hmma<0, 0><<<dim3(PPAD / 128, MB), 256, DSMEM>>>(hB, 512, w3, f2b3,
                                                          pa, nullptr, PDIM, 512);

    rqs_kernel<<<B, 64>>>(x, pa, nullptr, out, ld, 1, B);
}